// round 1
// baseline (speedup 1.0000x reference)
#include <cuda_runtime.h>
#include <cstdint>

#define NPTS 200000
#define CIN  256
#define CH   64
#define KK   27
#define MM   100000
#define BB   4
#define EPSN 1e-5f

typedef unsigned long long ull;

// ---------------- scratch (device globals: no allocation allowed) ----------
__device__ float g_x1 [(size_t)NPTS*CH];   // conv1 raw
__device__ float g_x1n[(size_t)NPTS*CH];   // conv1 normalized+relu
__device__ float g_x2 [(size_t)NPTS*CH];   // sparse conv accum (zeroed each call)
__device__ float g_x2n[(size_t)NPTS*CH];   // normalized+relu
__device__ float g_y3 [(size_t)NPTS*CIN];  // conv3 raw
__device__ float g_s1[2*BB*CH];
__device__ float g_s2[2*BB*CH];
__device__ float g_s3[2*BB*CIN];
__device__ float g_mr1[2*BB*CH];
__device__ float g_mr2[2*BB*CH];
__device__ float g_mr3[2*BB*CIN];
__device__ float g_cnt[BB];

// ---------------- packed fp32x2 helpers (Blackwell dual-fp32 pipe) ---------
__device__ __forceinline__ ull pack2(float lo, float hi) {
    ull r; asm("mov.b64 %0, {%1, %2};" : "=l"(r) : "f"(lo), "f"(hi)); return r;
}
__device__ __forceinline__ void fma2(ull &acc, ull a, ull b) {
    asm("fma.rn.f32x2 %0, %1, %2, %0;" : "+l"(acc) : "l"(a), "l"(b));
}
__device__ __forceinline__ float2 unpk(ull v) {
    float lo, hi; asm("mov.b64 {%0, %1}, %2;" : "=f"(lo), "=f"(hi) : "l"(v));
    return make_float2(lo, hi);
}
__device__ __forceinline__ void red_add_v4(float* a, float x, float y, float z, float w) {
    asm volatile("red.global.add.v4.f32 [%0], {%1,%2,%3,%4};"
                 :: "l"(a), "f"(x), "f"(y), "f"(z), "f"(w) : "memory");
}

// ---------------- init: zero scatter buffer + stats ------------------------
__global__ void k_init() {
    size_t i      = (size_t)blockIdx.x * blockDim.x + threadIdx.x;
    size_t stride = (size_t)gridDim.x * blockDim.x;
    float4* p = (float4*)g_x2;
    const size_t tot = (size_t)NPTS*CH/4;
    for (size_t j = i; j < tot; j += stride) p[j] = make_float4(0.f,0.f,0.f,0.f);
    if (i < 2*BB*CH)  { g_s1[i] = 0.f; g_s2[i] = 0.f; }
    if (i < 2*BB*CIN) g_s3[i] = 0.f;
    if (i < BB)       g_cnt[i] = 0.f;
}

__global__ void k_count(const int* __restrict__ bidx) {
    __shared__ int c[BB];
    int tid = threadIdx.x;
    if (tid < BB) c[tid] = 0;
    __syncthreads();
    int i = blockIdx.x * 256 + tid;
    if (i < NPTS) atomicAdd(&c[bidx[i]], 1);
    __syncthreads();
    if (tid < BB && c[tid] > 0) atomicAdd(&g_cnt[tid], (float)c[tid]);
}

// ---------------- GEMM1: [N,256] @ [256,64] -> g_x1 ------------------------
// block = 64 rows; thread = 4 rows x 4 cols; f32x2 accumulators.
__global__ void __launch_bounds__(256) k_gemm1(const float* __restrict__ feats,
                                               const float* __restrict__ W1) {
    extern __shared__ float sh[];
    float* xs = sh;               // [64][260]  (pad: bank-conflict-free)
    float* Ws = sh + 64*260;      // [256][64]
    int tid = threadIdx.x;
    int rbase = blockIdx.x * 64;

    const float4* Wg = (const float4*)W1;
    float4* Ws4 = (float4*)Ws;
    #pragma unroll
    for (int i = 0; i < 16; i++) Ws4[tid + 256*i] = Wg[tid + 256*i];

    const float4* fg = (const float4*)feats;
    #pragma unroll
    for (int i = 0; i < 16; i++) {
        int lin = tid + 256*i;
        int r = lin >> 6, c4 = lin & 63;
        float4 v = fg[(size_t)(rbase + r) * 64 + c4];
        *(float4*)&xs[r*260 + c4*4] = v;
    }
    __syncthreads();

    int dgrp = tid & 15, rg = tid >> 4;
    int d0 = dgrp * 4, r0 = rg * 4;
    ull acc[4][2] = {};
    const float* xb = &xs[r0*260];
    #pragma unroll 4
    for (int c = 0; c < 256; c++) {
        ulonglong2 w = *(const ulonglong2*)&Ws[c*64 + d0];
        #pragma unroll
        for (int j = 0; j < 4; j++) {
            float x = xb[j*260 + c];
            ull xp = pack2(x, x);
            fma2(acc[j][0], xp, w.x);
            fma2(acc[j][1], xp, w.y);
        }
    }
    #pragma unroll
    for (int j = 0; j < 4; j++) {
        float2 a = unpk(acc[j][0]), b = unpk(acc[j][1]);
        *(float4*)&g_x1[(size_t)(rbase + r0 + j)*CH + d0] = make_float4(a.x,a.y,b.x,b.y);
    }
}

// ---------------- stats over [N,64] -> sum/sumsq per (b,ch) ----------------
__global__ void k_stats64(const float* __restrict__ src, float* __restrict__ dst,
                          const int* __restrict__ bidx) {
    __shared__ float sacc[2*BB*CH];   // 512
    int tid = threadIdx.x;
    sacc[tid] = 0.f; sacc[tid + 256] = 0.f;
    __syncthreads();
    int ch = tid & 63, rsub = tid >> 6;
    int rbase = blockIdx.x * 512;
    int rend = rbase + 512; if (rend > NPTS) rend = NPTS;
    float ls = 0.f, lq = 0.f; int curb = -1;
    for (int r = rbase + rsub; r < rend; r += 4) {
        int b = bidx[r];
        if (b != curb) {
            if (curb >= 0) {
                atomicAdd(&sacc[curb*CH + ch], ls);
                atomicAdd(&sacc[BB*CH + curb*CH + ch], lq);
            }
            curb = b; ls = 0.f; lq = 0.f;
        }
        float v = src[(size_t)r*CH + ch];
        ls += v; lq += v*v;
    }
    if (curb >= 0) {
        atomicAdd(&sacc[curb*CH + ch], ls);
        atomicAdd(&sacc[BB*CH + curb*CH + ch], lq);
    }
    __syncthreads();
    atomicAdd(&dst[tid],       sacc[tid]);
    atomicAdd(&dst[tid + 256], sacc[tid + 256]);
}

// ---------------- stats over [N,256] ---------------------------------------
__global__ void k_stats256(const float* __restrict__ src, float* __restrict__ dst,
                           const int* __restrict__ bidx) {
    __shared__ float sacc[2*BB*CIN];  // 2048
    int tid = threadIdx.x;
    for (int i = tid; i < 2*BB*CIN; i += 256) sacc[i] = 0.f;
    __syncthreads();
    int rbase = blockIdx.x * 1024;
    int rend = rbase + 1024; if (rend > NPTS) rend = NPTS;
    float ls = 0.f, lq = 0.f; int curb = -1;
    for (int r = rbase; r < rend; r++) {
        int b = bidx[r];
        if (b != curb) {
            if (curb >= 0) { sacc[curb*CIN + tid] += ls; sacc[BB*CIN + curb*CIN + tid] += lq; }
            curb = b; ls = 0.f; lq = 0.f;
        }
        float v = src[(size_t)r*CIN + tid];
        ls += v; lq += v*v;
    }
    if (curb >= 0) { sacc[curb*CIN + tid] += ls; sacc[BB*CIN + curb*CIN + tid] += lq; }
    __syncthreads();
    for (int i = tid; i < 2*BB*CIN; i += 256) atomicAdd(&dst[i], sacc[i]);
}

// ---------------- finalize mean / rsig --------------------------------------
__global__ void k_fin(const float* __restrict__ s, float* __restrict__ mr, int C) {
    int i = blockIdx.x * blockDim.x + threadIdx.x;
    int tot = BB * C;
    if (i >= tot) return;
    int b = i / C;
    float cnt  = g_cnt[b];
    float mean = s[i] / cnt;
    float var  = s[tot + i] / cnt - mean * mean;
    mr[i]       = mean;
    mr[tot + i] = rsqrtf(fmaxf(var, 0.f) + EPSN);
}

// ---------------- normalize + relu into dst ([N,64]) ------------------------
__global__ void k_normrelu(const float* __restrict__ src, const float* __restrict__ mr,
                           float* __restrict__ dst, const int* __restrict__ bidx) {
    int i4 = blockIdx.x * blockDim.x + threadIdx.x;
    const int tot = NPTS*CH/4;
    int stride = gridDim.x * blockDim.x;
    const float4* s4 = (const float4*)src;
    const float4* m4 = (const float4*)mr;
    const float4* r4 = (const float4*)(mr + BB*CH);
    float4* d4 = (float4*)dst;
    for (; i4 < tot; i4 += stride) {
        int r = i4 >> 4, c4 = i4 & 15;
        int b = bidx[r];
        float4 m = m4[b*16 + c4], rs = r4[b*16 + c4];
        float4 x = s4[i4];
        float4 o;
        o.x = fmaxf((x.x - m.x)*rs.x, 0.f);
        o.y = fmaxf((x.y - m.y)*rs.y, 0.f);
        o.z = fmaxf((x.z - m.z)*rs.z, 0.f);
        o.w = fmaxf((x.w - m.w)*rs.w, 0.f);
        d4[i4] = o;
    }
}

// ---------------- sparse conv: gather-GEMM-scatter --------------------------
// grid: (ceil(M/640), 27).  Block holds W2[k] (16KB) + 64-pair staging.
__global__ void __launch_bounds__(256) k_spconv(const float* __restrict__ W2,
                                                const int* __restrict__ in_idx,
                                                const int* __restrict__ out_idx) {
    __shared__ float Ws[CH*CH];      // [c][d]
    __shared__ float xs[64*68];      // 64 pairs x 64 ch, padded stride 68
    __shared__ int   sin_[64], sout_[64];
    int tid = threadIdx.x;
    int k = blockIdx.y;
    const float4* Wg = (const float4*)(W2 + (size_t)k*CH*CH);
    #pragma unroll
    for (int i = 0; i < 4; i++) ((float4*)Ws)[tid + 256*i] = Wg[tid + 256*i];

    int dgrp = tid & 15, pg = tid >> 4;
    int d0 = dgrp * 4;
    int mstart = blockIdx.x * 640;

    for (int ph = 0; ph < 10; ph++) {
        int m0 = mstart + ph*64;
        __syncthreads();   // protect xs/sout reuse (and orders Ws on ph=0)
        if (tid < 64) {
            int m = m0 + tid;
            sin_[tid] = (m < MM) ? in_idx[(size_t)k*MM + m] : -1;
        } else if (tid < 128) {
            int m = m0 + (tid - 64);
            sout_[tid - 64] = (m < MM) ? out_idx[(size_t)k*MM + m] : -1;
        }
        __syncthreads();
        #pragma unroll
        for (int i = 0; i < 16; i++) {
            int lin = tid + 256*i;
            int p = lin >> 6, c = lin & 63;
            int row = sin_[p];
            xs[p*68 + c] = (row >= 0) ? g_x1n[(size_t)row*CH + c] : 0.f;
        }
        __syncthreads();
        ull acc[4][2] = {};
        #pragma unroll 4
        for (int c = 0; c < 64; c++) {
            ulonglong2 w = *(const ulonglong2*)&Ws[c*64 + d0];
            #pragma unroll
            for (int j = 0; j < 4; j++) {
                float x = xs[(pg*4 + j)*68 + c];
                ull xp = pack2(x, x);
                fma2(acc[j][0], xp, w.x);
                fma2(acc[j][1], xp, w.y);
            }
        }
        #pragma unroll
        for (int j = 0; j < 4; j++) {
            int row = sout_[pg*4 + j];
            if (row >= 0) {
                float2 a = unpk(acc[j][0]), b = unpk(acc[j][1]);
                red_add_v4(&g_x2[(size_t)row*CH + d0], a.x, a.y, b.x, b.y);
            }
        }
    }
}

// ---------------- GEMM3: [N,64] @ [64,256] -> g_y3 --------------------------
// block = 64 rows; thread = 16 rows x 4 cols (xs reads are warp-broadcast).
__global__ void __launch_bounds__(256) k_gemm3(const float* __restrict__ W3) {
    extern __shared__ float sh[];
    float* xs = sh;              // [64][64]
    float* Ws = sh + 64*64;      // [64][256]
    int tid = threadIdx.x;
    int rbase = blockIdx.x * 64;

    const float4* Wg = (const float4*)W3;
    float4* Ws4 = (float4*)Ws;
    #pragma unroll
    for (int i = 0; i < 16; i++) Ws4[tid + 256*i] = Wg[tid + 256*i];

    const float4* xg = (const float4*)g_x2n;
    #pragma unroll
    for (int i = 0; i < 4; i++) {
        int lin = tid + 256*i;       // 1024 float4
        int r = lin >> 4, c4 = lin & 15;
        ((float4*)xs)[r*16 + c4] = xg[(size_t)(rbase + r)*16 + c4];
    }
    __syncthreads();

    int dgrp = tid & 63, rg = tid >> 6;
    int d0 = dgrp * 4, r0 = rg * 16;
    ull acc[16][2] = {};
    for (int c = 0; c < 64; c++) {
        ulonglong2 w = *(const ulonglong2*)&Ws[c*256 + d0];
        #pragma unroll
        for (int j = 0; j < 16; j++) {
            float x = xs[(r0 + j)*64 + c];   // warp-uniform -> broadcast
            ull xp = pack2(x, x);
            fma2(acc[j][0], xp, w.x);
            fma2(acc[j][1], xp, w.y);
        }
    }
    #pragma unroll
    for (int j = 0; j < 16; j++) {
        float2 a = unpk(acc[j][0]), b = unpk(acc[j][1]);
        *(float4*)&g_y3[(size_t)(rbase + r0 + j)*CIN + d0] = make_float4(a.x,a.y,b.x,b.y);
    }
}

// ---------------- final: relu(IN(y3) + feats) -> out -----------------------
__global__ void k_final(const float* __restrict__ feats, const int* __restrict__ bidx,
                        float* __restrict__ out) {
    int i4 = blockIdx.x * blockDim.x + threadIdx.x;
    const int tot = NPTS*CIN/4;   // 12.8M
    int stride = gridDim.x * blockDim.x;
    const float4* y4 = (const float4*)g_y3;
    const float4* f4 = (const float4*)feats;
    const float4* m4 = (const float4*)g_mr3;
    const float4* r4 = (const float4*)(g_mr3 + BB*CIN);
    float4* o4 = (float4*)out;
    for (; i4 < tot; i4 += stride) {
        int r = i4 >> 6, c4 = i4 & 63;
        int b = bidx[r];
        float4 m = m4[b*64 + c4], rs = r4[b*64 + c4];
        float4 y = y4[i4], f = f4[i4];
        float4 o;
        o.x = fmaxf((y.x - m.x)*rs.x + f.x, 0.f);
        o.y = fmaxf((y.y - m.y)*rs.y + f.y, 0.f);
        o.z = fmaxf((y.z - m.z)*rs.z + f.z, 0.f);
        o.w = fmaxf((y.w - m.w)*rs.w + f.w, 0.f);
        o4[i4] = o;
    }
}

// ---------------- launch ----------------------------------------------------
extern "C" void kernel_launch(void* const* d_in, const int* in_sizes, int n_in,
                              void* d_out, int out_size) {
    const float* feats  = (const float*)d_in[0];
    const float* W1     = (const float*)d_in[1];
    const float* W2     = (const float*)d_in[2];
    const float* W3     = (const float*)d_in[3];
    const int*   in_idx = (const int*)d_in[4];
    const int*   out_idx= (const int*)d_in[5];
    const int*   bidx   = (const int*)d_in[6];
    float* out = (float*)d_out;

    const int smem1 = 64*260*4 + 256*64*4;   // 132096
    const int smem3 = 64*64*4  + 64*256*4;   //  81920
    cudaFuncSetAttribute(k_gemm1, cudaFuncAttributeMaxDynamicSharedMemorySize, smem1);
    cudaFuncSetAttribute(k_gemm3, cudaFuncAttributeMaxDynamicSharedMemorySize, smem3);

    float *p_x1, *p_x1n, *p_x2, *p_x2n, *p_y3;
    float *p_s1, *p_s2, *p_s3, *p_mr1, *p_mr2, *p_mr3;
    cudaGetSymbolAddress((void**)&p_x1,  g_x1);
    cudaGetSymbolAddress((void**)&p_x1n, g_x1n);
    cudaGetSymbolAddress((void**)&p_x2,  g_x2);
    cudaGetSymbolAddress((void**)&p_x2n, g_x2n);
    cudaGetSymbolAddress((void**)&p_y3,  g_y3);
    cudaGetSymbolAddress((void**)&p_s1,  g_s1);
    cudaGetSymbolAddress((void**)&p_s2,  g_s2);
    cudaGetSymbolAddress((void**)&p_s3,  g_s3);
    cudaGetSymbolAddress((void**)&p_mr1, g_mr1);
    cudaGetSymbolAddress((void**)&p_mr2, g_mr2);
    cudaGetSymbolAddress((void**)&p_mr3, g_mr3);

    k_init<<<256, 256>>>();
    k_count<<<(NPTS + 255)/256, 256>>>(bidx);

    // conv1 -> IN -> relu
    k_gemm1<<<NPTS/64, 256, smem1>>>(feats, W1);
    k_stats64<<<(NPTS + 511)/512, 256>>>(p_x1, p_s1, bidx);
    k_fin<<<1, 256>>>(p_s1, p_mr1, CH);
    k_normrelu<<<2048, 256>>>(p_x1, p_mr1, p_x1n, bidx);

    // sparse conv -> IN -> relu
    dim3 spgrid((MM + 639)/640, KK);
    k_spconv<<<spgrid, 256>>>(W2, in_idx, out_idx);
    k_stats64<<<(NPTS + 511)/512, 256>>>(p_x2, p_s2, bidx);
    k_fin<<<1, 256>>>(p_s2, p_mr2, CH);
    k_normrelu<<<2048, 256>>>(p_x2, p_mr2, p_x2n, bidx);

    // conv3 -> IN -> residual -> relu
    k_gemm3<<<NPTS/64, 256, smem3>>>(W3);
    k_stats256<<<(NPTS + 1023)/1024, 256>>>(p_y3, p_s3, bidx);
    k_fin<<<4, 256>>>(p_s3, p_mr3, CIN);
    k_final<<<4096, 256>>>(feats, bidx, out);
}

// round 2
// speedup vs baseline: 1.3855x; 1.3855x over previous
#include <cuda_runtime.h>
#include <cstdint>

#define NPTS 200000
#define CIN  256
#define CH   64
#define KK   27
#define MM   100000
#define BB   4
#define EPSN 1e-5f

typedef unsigned long long ull;

// ---------------- scratch (device globals) ----------------------------------
__device__ float g_x1 [(size_t)NPTS*CH];
__device__ float g_x1n[(size_t)NPTS*CH];
__device__ float g_x2 [(size_t)NPTS*CH];
__device__ float g_y3 [(size_t)NPTS*CIN];
__device__ float g_s1[2*BB*CH];
__device__ float g_s2[2*BB*CH];
__device__ float g_s3[2*BB*CIN];
__device__ float g_mr1[2*BB*CH];
__device__ float g_mr2[2*BB*CH];
__device__ float g_mr3[2*BB*CIN];
__device__ int   g_bnd[BB+1];

// ---------------- packed fp32x2 helpers -------------------------------------
__device__ __forceinline__ ull pack2(float lo, float hi) {
    ull r; asm("mov.b64 %0, {%1, %2};" : "=l"(r) : "f"(lo), "f"(hi)); return r;
}
__device__ __forceinline__ void fma2(ull &acc, ull a, ull b) {
    asm("fma.rn.f32x2 %0, %1, %2, %0;" : "+l"(acc) : "l"(a), "l"(b));
}
__device__ __forceinline__ float2 unpk(ull v) {
    float lo, hi; asm("mov.b64 {%0, %1}, %2;" : "=f"(lo), "=f"(hi) : "l"(v));
    return make_float2(lo, hi);
}
__device__ __forceinline__ void red_add_v4(float* a, float x, float y, float z, float w) {
    asm volatile("red.global.add.v4.f32 [%0], {%1,%2,%3,%4};"
                 :: "l"(a), "f"(x), "f"(y), "f"(z), "f"(w) : "memory");
}

// ---------------- init: zero scatter buffer + stats + bounds ----------------
__global__ void k_init() {
    size_t i      = (size_t)blockIdx.x * blockDim.x + threadIdx.x;
    size_t stride = (size_t)gridDim.x * blockDim.x;
    float4* p = (float4*)g_x2;
    const size_t tot = (size_t)NPTS*CH/4;
    for (size_t j = i; j < tot; j += stride) p[j] = make_float4(0.f,0.f,0.f,0.f);
    if (i < 2*BB*CH)  { g_s1[i] = 0.f; g_s2[i] = 0.f; }
    if (i < 2*BB*CIN) g_s3[i] = 0.f;
    if (i == 0) g_bnd[0] = 0;
    if (i >= 1 && i <= BB) g_bnd[i] = NPTS;
}

// batch_idx is sorted; record segment starts.
__global__ void k_bounds(const int* __restrict__ bidx) {
    int i = blockIdx.x * 256 + threadIdx.x;
    if (i >= NPTS) return;
    int b = bidx[i];
    if (i == 0) {
        for (int t = 1; t <= b; t++) g_bnd[t] = 0;
    } else {
        int pb = bidx[i-1];
        for (int t = pb + 1; t <= b; t++) g_bnd[t] = i;
    }
}

// ---------------- GEMM1: [N,256] @ [256,64] -> g_x1 -------------------------
// 128 rows/block, K-chunked (4x64), thread = 4 rows x 8 cols, swizzled xs.
__global__ void __launch_bounds__(256) k_gemm1(const float* __restrict__ feats,
                                               const float* __restrict__ W1) {
    extern __shared__ float sh[];
    float* Ws = sh;              // [256][64] = 64KB
    float* xs = sh + 256*64;     // [128][64] = 32KB, XOR-swizzled
    int tid = threadIdx.x;
    int rbase = blockIdx.x * 128;

    const float4* Wg = (const float4*)W1;
    float4* Ws4 = (float4*)Ws;
    #pragma unroll
    for (int i = 0; i < 16; i++) Ws4[tid + 256*i] = Wg[tid + 256*i];

    int dg = tid & 7, rg = tid >> 3;      // 8 col-groups x 32 row-groups
    int r0 = rg * 4, col0 = dg * 8;
    int Kx = rg & 7;                      // swizzle key (= r>>2 for rows r0..r0+3)
    ull acc[4][4] = {};
    const float4* fg = (const float4*)feats;
    float4* xs4 = (float4*)xs;

    for (int kk = 0; kk < 4; kk++) {
        __syncthreads();
        #pragma unroll
        for (int i = 0; i < 8; i++) {
            int lin = tid + 256*i;
            int r = lin >> 4, c4 = lin & 15;
            int gr = rbase + r;
            float4 v = (gr < NPTS) ? fg[(size_t)gr*64 + kk*16 + c4]
                                   : make_float4(0.f,0.f,0.f,0.f);
            xs4[r*16 + (c4 ^ ((r >> 2) & 7))] = v;
        }
        __syncthreads();
        #pragma unroll 4
        for (int c = 0; c < 64; c++) {
            const ulonglong2* wp = (const ulonglong2*)&Ws[(kk*64 + c)*64 + col0];
            ulonglong2 wA = wp[0], wB = wp[1];
            int xoff = (((c >> 2) ^ Kx) << 2) + (c & 3);
            #pragma unroll
            for (int j = 0; j < 4; j++) {
                float x = xs[(r0 + j)*64 + xoff];
                ull xp = pack2(x, x);
                fma2(acc[j][0], xp, wA.x); fma2(acc[j][1], xp, wA.y);
                fma2(acc[j][2], xp, wB.x); fma2(acc[j][3], xp, wB.y);
            }
        }
    }
    #pragma unroll
    for (int j = 0; j < 4; j++) {
        int gr = rbase + r0 + j;
        if (gr < NPTS) {
            float2 a = unpk(acc[j][0]), b = unpk(acc[j][1]);
            float2 c = unpk(acc[j][2]), d = unpk(acc[j][3]);
            *(float4*)&g_x1[(size_t)gr*CH + col0]     = make_float4(a.x,a.y,b.x,b.y);
            *(float4*)&g_x1[(size_t)gr*CH + col0 + 4] = make_float4(c.x,c.y,d.x,d.y);
        }
    }
}

// ---------------- branch-free segmented stats --------------------------------
template<int C, int RPB>
__global__ void __launch_bounds__(256) k_stats(const float* __restrict__ src,
                                               float* __restrict__ dst) {
    __shared__ float sacc[2*BB*C];
    int tid = threadIdx.x;
    for (int i = tid; i < 2*BB*C; i += 256) sacc[i] = 0.f;
    __syncthreads();
    const int SUB = 256 / C;
    int ch = tid & (C-1);
    int sr = tid / C;
    int rbase = blockIdx.x * RPB;
    int rend = rbase + RPB; if (rend > NPTS) rend = NPTS;
    #pragma unroll
    for (int s = 0; s < BB; s++) {
        int lo = g_bnd[s];   if (lo < rbase) lo = rbase;
        int hi = g_bnd[s+1]; if (hi > rend)  hi = rend;
        float ls = 0.f, lq = 0.f;
        #pragma unroll 4
        for (int r = lo + sr; r < hi; r += SUB) {
            float v = src[(size_t)r*C + ch];
            ls += v; lq += v*v;
        }
        if (lo < hi) {
            atomicAdd(&sacc[s*C + ch], ls);
            atomicAdd(&sacc[BB*C + s*C + ch], lq);
        }
    }
    __syncthreads();
    for (int i = tid; i < 2*BB*C; i += 256) atomicAdd(&dst[i], sacc[i]);
}

// ---------------- finalize mean / rsig ---------------------------------------
__global__ void k_fin(const float* __restrict__ s, float* __restrict__ mr, int C) {
    int i = blockIdx.x * blockDim.x + threadIdx.x;
    int tot = BB * C;
    if (i >= tot) return;
    int b = i / C;
    float cnt = (float)(g_bnd[b+1] - g_bnd[b]);
    float inv = cnt > 0.f ? 1.f / cnt : 0.f;
    float mean = s[i] * inv;
    float var  = s[tot + i] * inv - mean * mean;
    mr[i]       = mean;
    mr[tot + i] = rsqrtf(fmaxf(var, 0.f) + EPSN);
}

// ---------------- normalize + relu ([N,64]) ----------------------------------
__global__ void k_normrelu(const float* __restrict__ src, const float* __restrict__ mr,
                           float* __restrict__ dst, const int* __restrict__ bidx) {
    int i4 = blockIdx.x * blockDim.x + threadIdx.x;
    const int tot = NPTS*CH/4;
    int stride = gridDim.x * blockDim.x;
    const float4* s4 = (const float4*)src;
    const float4* m4 = (const float4*)mr;
    const float4* r4 = (const float4*)(mr + BB*CH);
    float4* d4 = (float4*)dst;
    for (; i4 < tot; i4 += stride) {
        int r = i4 >> 4, c4 = i4 & 15;
        int b = bidx[r];
        float4 m = m4[b*16 + c4], rs = r4[b*16 + c4];
        float4 x = s4[i4];
        float4 o;
        o.x = fmaxf((x.x - m.x)*rs.x, 0.f);
        o.y = fmaxf((x.y - m.y)*rs.y, 0.f);
        o.z = fmaxf((x.z - m.z)*rs.z, 0.f);
        o.w = fmaxf((x.w - m.w)*rs.w, 0.f);
        d4[i4] = o;
    }
}

// ---------------- sparse conv: register-resident gather-GEMM-scatter ---------
// Thread = 2 pairs x 32 cols. No x staging, no per-phase barriers.
__global__ void __launch_bounds__(256, 2) k_spconv(const float* __restrict__ W2,
                                                   const int* __restrict__ in_idx,
                                                   const int* __restrict__ out_idx) {
    __shared__ float Ws[CH*CH];      // [c][d], 16KB
    int tid = threadIdx.x;
    int k = blockIdx.y;
    const float4* Wg = (const float4*)(W2 + (size_t)k*CH*CH);
    #pragma unroll
    for (int i = 0; i < 4; i++) ((float4*)Ws)[tid + 256*i] = Wg[tid + 256*i];
    __syncthreads();

    int slot = tid >> 1, dg = tid & 1;
    int col0 = dg * 32;
    size_t kb = (size_t)k * MM;
    int m0 = blockIdx.x * 256;
    int pA = m0 + slot;              // always < MM (grid sized so)
    int pB = pA + 128;
    bool vB = pB < MM;
    int ra = in_idx[kb + pA];
    int rb = vB ? in_idx[kb + pB] : 0;
    int oa = out_idx[kb + pA];
    int ob = vB ? out_idx[kb + pB] : 0;
    const float4* xa = (const float4*)(g_x1n + (size_t)ra*CH);
    const float4* xb = (const float4*)(g_x1n + (size_t)rb*CH);

    ull acc[2][16] = {};
    #pragma unroll 2
    for (int c4 = 0; c4 < 16; c4++) {
        float4 va = xa[c4];
        float4 vv = vB ? xb[c4] : make_float4(0.f,0.f,0.f,0.f);
        float fa[4] = {va.x, va.y, va.z, va.w};
        float fb[4] = {vv.x, vv.y, vv.z, vv.w};
        #pragma unroll
        for (int e = 0; e < 4; e++) {
            const ulonglong2* wp = (const ulonglong2*)&Ws[(c4*4 + e)*CH + col0];
            ulonglong2 wv[8];
            #pragma unroll
            for (int i = 0; i < 8; i++) wv[i] = wp[i];
            ull ap = pack2(fa[e], fa[e]);
            ull bp = pack2(fb[e], fb[e]);
            #pragma unroll
            for (int i = 0; i < 8; i++) {
                fma2(acc[0][2*i],   ap, wv[i].x);
                fma2(acc[0][2*i+1], ap, wv[i].y);
                fma2(acc[1][2*i],   bp, wv[i].x);
                fma2(acc[1][2*i+1], bp, wv[i].y);
            }
        }
    }
    float* outA = &g_x2[(size_t)oa*CH + col0];
    #pragma unroll
    for (int q = 0; q < 8; q++) {
        float2 a = unpk(acc[0][2*q]), b = unpk(acc[0][2*q+1]);
        red_add_v4(outA + q*4, a.x, a.y, b.x, b.y);
    }
    if (vB) {
        float* outB = &g_x2[(size_t)ob*CH + col0];
        #pragma unroll
        for (int q = 0; q < 8; q++) {
            float2 a = unpk(acc[1][2*q]), b = unpk(acc[1][2*q+1]);
            red_add_v4(outB + q*4, a.x, a.y, b.x, b.y);
        }
    }
}

// ---------------- GEMM3: relu(IN(x2)) @ [64,256] -> g_y3 (norm fused) --------
// 64 rows/block, thread = 4 rows x 16 cols, pad-68 xs.
__global__ void __launch_bounds__(256, 2) k_gemm3(const float* __restrict__ W3,
                                                  const int* __restrict__ bidx) {
    extern __shared__ float sh[];
    float* Ws = sh;              // [64][256] = 64KB
    float* xs = sh + 64*256;     // [64][68]  = 17.4KB
    int tid = threadIdx.x;
    int rbase = blockIdx.x * 64;

    const float4* Wg = (const float4*)W3;
    float4* Ws4 = (float4*)Ws;
    #pragma unroll
    for (int i = 0; i < 16; i++) Ws4[tid + 256*i] = Wg[tid + 256*i];

    // load x2 tile + fused IN+ReLU
    const float4* m4 = (const float4*)g_mr2;
    const float4* r4 = (const float4*)(g_mr2 + BB*CH);
    const float4* xg = (const float4*)g_x2;
    #pragma unroll
    for (int i = 0; i < 4; i++) {
        int lin = tid + 256*i;
        int r = lin >> 4, c4 = lin & 15;
        int gr = rbase + r;
        int b = bidx[gr];
        float4 v = xg[(size_t)gr*16 + c4];
        float4 m = m4[b*16 + c4], rs = r4[b*16 + c4];
        float4 o;
        o.x = fmaxf((v.x - m.x)*rs.x, 0.f);
        o.y = fmaxf((v.y - m.y)*rs.y, 0.f);
        o.z = fmaxf((v.z - m.z)*rs.z, 0.f);
        o.w = fmaxf((v.w - m.w)*rs.w, 0.f);
        *(float4*)&xs[r*68 + c4*4] = o;
    }
    __syncthreads();

    int dg = tid & 15, rg = tid >> 4;
    int r0 = rg * 4, col0 = dg * 16;
    ull acc[4][8] = {};
    #pragma unroll 4
    for (int c = 0; c < 64; c++) {
        const ulonglong2* wp = (const ulonglong2*)&Ws[c*256 + col0];
        ulonglong2 w0 = wp[0], w1 = wp[1], w2 = wp[2], w3 = wp[3];
        #pragma unroll
        for (int j = 0; j < 4; j++) {
            float x = xs[(r0 + j)*68 + c];
            ull xp = pack2(x, x);
            fma2(acc[j][0], xp, w0.x); fma2(acc[j][1], xp, w0.y);
            fma2(acc[j][2], xp, w1.x); fma2(acc[j][3], xp, w1.y);
            fma2(acc[j][4], xp, w2.x); fma2(acc[j][5], xp, w2.y);
            fma2(acc[j][6], xp, w3.x); fma2(acc[j][7], xp, w3.y);
        }
    }
    #pragma unroll
    for (int j = 0; j < 4; j++) {
        float* dst = &g_y3[(size_t)(rbase + r0 + j)*CIN + col0];
        #pragma unroll
        for (int q = 0; q < 4; q++) {
            float2 a = unpk(acc[j][2*q]), b = unpk(acc[j][2*q+1]);
            *(float4*)(dst + q*4) = make_float4(a.x, a.y, b.x, b.y);
        }
    }
}

// ---------------- final: relu(IN(y3) + feats) -> out -------------------------
__global__ void k_final(const float* __restrict__ feats, const int* __restrict__ bidx,
                        float* __restrict__ out) {
    int i4 = blockIdx.x * blockDim.x + threadIdx.x;
    const int tot = NPTS*CIN/4;
    int stride = gridDim.x * blockDim.x;
    const float4* y4 = (const float4*)g_y3;
    const float4* f4 = (const float4*)feats;
    const float4* m4 = (const float4*)g_mr3;
    const float4* r4 = (const float4*)(g_mr3 + BB*CIN);
    float4* o4 = (float4*)out;
    for (; i4 < tot; i4 += stride) {
        int r = i4 >> 6, c4 = i4 & 63;
        int b = bidx[r];
        float4 m = m4[b*64 + c4], rs = r4[b*64 + c4];
        float4 y = y4[i4], f = f4[i4];
        float4 o;
        o.x = fmaxf((y.x - m.x)*rs.x + f.x, 0.f);
        o.y = fmaxf((y.y - m.y)*rs.y + f.y, 0.f);
        o.z = fmaxf((y.z - m.z)*rs.z + f.z, 0.f);
        o.w = fmaxf((y.w - m.w)*rs.w + f.w, 0.f);
        o4[i4] = o;
    }
}

// ---------------- launch -----------------------------------------------------
extern "C" void kernel_launch(void* const* d_in, const int* in_sizes, int n_in,
                              void* d_out, int out_size) {
    const float* feats   = (const float*)d_in[0];
    const float* W1      = (const float*)d_in[1];
    const float* W2      = (const float*)d_in[2];
    const float* W3      = (const float*)d_in[3];
    const int*   in_idx  = (const int*)d_in[4];
    const int*   out_idx = (const int*)d_in[5];
    const int*   bidx    = (const int*)d_in[6];
    float* out = (float*)d_out;

    const int smem1 = (256*64 + 128*64) * 4;   // 98304
    const int smem3 = (64*256 + 64*68) * 4;    // 82944
    cudaFuncSetAttribute(k_gemm1, cudaFuncAttributeMaxDynamicSharedMemorySize, smem1);
    cudaFuncSetAttribute(k_gemm3, cudaFuncAttributeMaxDynamicSharedMemorySize, smem3);

    float *p_x1, *p_x1n, *p_x2, *p_y3;
    float *p_s1, *p_s2, *p_s3, *p_mr1, *p_mr2, *p_mr3;
    cudaGetSymbolAddress((void**)&p_x1,  g_x1);
    cudaGetSymbolAddress((void**)&p_x1n, g_x1n);
    cudaGetSymbolAddress((void**)&p_x2,  g_x2);
    cudaGetSymbolAddress((void**)&p_y3,  g_y3);
    cudaGetSymbolAddress((void**)&p_s1,  g_s1);
    cudaGetSymbolAddress((void**)&p_s2,  g_s2);
    cudaGetSymbolAddress((void**)&p_s3,  g_s3);
    cudaGetSymbolAddress((void**)&p_mr1, g_mr1);
    cudaGetSymbolAddress((void**)&p_mr2, g_mr2);
    cudaGetSymbolAddress((void**)&p_mr3, g_mr3);

    k_init<<<512, 256>>>();
    k_bounds<<<(NPTS + 255)/256, 256>>>(bidx);

    // conv1 -> IN -> relu
    k_gemm1<<<(NPTS + 127)/128, 256, smem1>>>(feats, W1);
    k_stats<CH, 1024><<<(NPTS + 1023)/1024, 256>>>(p_x1, p_s1);
    k_fin<<<1, 256>>>(p_s1, p_mr1, CH);
    k_normrelu<<<2048, 256>>>(p_x1, p_mr1, p_x1n, bidx);

    // sparse conv -> (stats)
    dim3 spgrid((MM + 255)/256, KK);
    k_spconv<<<spgrid, 256>>>(W2, in_idx, out_idx);
    k_stats<CH, 1024><<<(NPTS + 1023)/1024, 256>>>(p_x2, p_s2);
    k_fin<<<1, 256>>>(p_s2, p_mr2, CH);

    // conv3 (IN+relu of x2 fused into tile load) -> IN -> residual -> relu
    k_gemm3<<<NPTS/64, 256, smem3>>>(W3, bidx);
    k_stats<CIN, 256><<<(NPTS + 255)/256, 256>>>(p_y3, p_s3);
    k_fin<<<4, 256>>>(p_s3, p_mr3, CIN);
    k_final<<<4096, 256>>>(feats, bidx, out);
}

// round 3
// speedup vs baseline: 1.5656x; 1.1300x over previous
#include <cuda_runtime.h>
#include <cstdint>

#define NPTS 200000
#define CIN  256
#define CH   64
#define KK   27
#define MM   100000
#define BB   4
#define EPSN 1e-5f

typedef unsigned long long ull;

// ---------------- scratch (device globals) ----------------------------------
__device__ float g_x1 [(size_t)NPTS*CH];
__device__ float g_x1n[(size_t)NPTS*CH];
__device__ float g_x2 [(size_t)NPTS*CH];
__device__ float g_y3 [(size_t)NPTS*CIN];
__device__ float g_s1[2*BB*CH];
__device__ float g_s2[2*BB*CH];
__device__ float g_s3[2*BB*CIN];
__device__ float g_mr1[2*BB*CH];
__device__ float g_mr2[2*BB*CH];
__device__ float g_mr3[2*BB*CIN];
__device__ int   g_bnd[BB+1];

// ---------------- packed fp32x2 helpers -------------------------------------
__device__ __forceinline__ ull pack2(float lo, float hi) {
    ull r; asm("mov.b64 %0, {%1, %2};" : "=l"(r) : "f"(lo), "f"(hi)); return r;
}
__device__ __forceinline__ void fma2(ull &acc, ull a, ull b) {
    asm("fma.rn.f32x2 %0, %1, %2, %0;" : "+l"(acc) : "l"(a), "l"(b));
}
__device__ __forceinline__ float2 unpk(ull v) {
    float lo, hi; asm("mov.b64 {%0, %1}, %2;" : "=f"(lo), "=f"(hi) : "l"(v));
    return make_float2(lo, hi);
}
__device__ __forceinline__ void red_add_v4(float* a, float x, float y, float z, float w) {
    asm volatile("red.global.add.v4.f32 [%0], {%1,%2,%3,%4};"
                 :: "l"(a), "f"(x), "f"(y), "f"(z), "f"(w) : "memory");
}

// ---------------- init: zero scatter buffer + stats + bounds ----------------
__global__ void k_init() {
    size_t i      = (size_t)blockIdx.x * blockDim.x + threadIdx.x;
    size_t stride = (size_t)gridDim.x * blockDim.x;
    float4* p = (float4*)g_x2;
    const size_t tot = (size_t)NPTS*CH/4;
    for (size_t j = i; j < tot; j += stride) p[j] = make_float4(0.f,0.f,0.f,0.f);
    if (i < 2*BB*CH)  { g_s1[i] = 0.f; g_s2[i] = 0.f; }
    if (i < 2*BB*CIN) g_s3[i] = 0.f;
    if (i == 0) g_bnd[0] = 0;
    if (i >= 1 && i <= BB) g_bnd[i] = NPTS;
}

__global__ void k_bounds(const int* __restrict__ bidx) {
    int i = blockIdx.x * 256 + threadIdx.x;
    if (i >= NPTS) return;
    int b = bidx[i];
    if (i == 0) {
        for (int t = 1; t <= b; t++) g_bnd[t] = 0;
    } else {
        int pb = bidx[i-1];
        for (int t = pb + 1; t <= b; t++) g_bnd[t] = i;
    }
}

// ---------------- GEMM1: [N,256] @ [256,64] -> g_x1 -------------------------
__global__ void __launch_bounds__(256) k_gemm1(const float* __restrict__ feats,
                                               const float* __restrict__ W1) {
    extern __shared__ float sh[];
    float* Ws = sh;              // [256][64]
    float* xs = sh + 256*64;     // [128][64], XOR-swizzled
    int tid = threadIdx.x;
    int rbase = blockIdx.x * 128;

    const float4* Wg = (const float4*)W1;
    float4* Ws4 = (float4*)Ws;
    #pragma unroll
    for (int i = 0; i < 16; i++) Ws4[tid + 256*i] = Wg[tid + 256*i];

    int dg = tid & 7, rg = tid >> 3;
    int r0 = rg * 4, col0 = dg * 8;
    int Kx = rg & 7;
    ull acc[4][4] = {};
    const float4* fg = (const float4*)feats;
    float4* xs4 = (float4*)xs;

    for (int kk = 0; kk < 4; kk++) {
        __syncthreads();
        #pragma unroll
        for (int i = 0; i < 8; i++) {
            int lin = tid + 256*i;
            int r = lin >> 4, c4 = lin & 15;
            int gr = rbase + r;
            float4 v = (gr < NPTS) ? fg[(size_t)gr*64 + kk*16 + c4]
                                   : make_float4(0.f,0.f,0.f,0.f);
            xs4[r*16 + (c4 ^ ((r >> 2) & 7))] = v;
        }
        __syncthreads();
        #pragma unroll 4
        for (int c = 0; c < 64; c++) {
            const ulonglong2* wp = (const ulonglong2*)&Ws[(kk*64 + c)*64 + col0];
            ulonglong2 wA = wp[0], wB = wp[1];
            int xoff = (((c >> 2) ^ Kx) << 2) + (c & 3);
            #pragma unroll
            for (int j = 0; j < 4; j++) {
                float x = xs[(r0 + j)*64 + xoff];
                ull xp = pack2(x, x);
                fma2(acc[j][0], xp, wA.x); fma2(acc[j][1], xp, wA.y);
                fma2(acc[j][2], xp, wB.x); fma2(acc[j][3], xp, wB.y);
            }
        }
    }
    #pragma unroll
    for (int j = 0; j < 4; j++) {
        int gr = rbase + r0 + j;
        if (gr < NPTS) {
            float2 a = unpk(acc[j][0]), b = unpk(acc[j][1]);
            float2 c = unpk(acc[j][2]), d = unpk(acc[j][3]);
            *(float4*)&g_x1[(size_t)gr*CH + col0]     = make_float4(a.x,a.y,b.x,b.y);
            *(float4*)&g_x1[(size_t)gr*CH + col0 + 4] = make_float4(c.x,c.y,d.x,d.y);
        }
    }
}

// ---------------- segmented stats, float4 loads ------------------------------
template<int C, int RPB>
__global__ void __launch_bounds__(256) k_stats(const float* __restrict__ src,
                                               float* __restrict__ dst) {
    const int G = C/4;           // float4 col groups
    const int SUB = 256/G;       // parallel row lanes
    __shared__ float sacc[2*BB*C];
    int tid = threadIdx.x;
    for (int i = tid; i < 2*BB*C; i += 256) sacc[i] = 0.f;
    __syncthreads();
    int g = tid % G, sr = tid / G;
    int rbase = blockIdx.x * RPB;
    int rend = rbase + RPB; if (rend > NPTS) rend = NPTS;
    const float4* s4 = (const float4*)src;
    #pragma unroll
    for (int s = 0; s < BB; s++) {
        int lo = g_bnd[s];   if (lo < rbase) lo = rbase;
        int hi = g_bnd[s+1]; if (hi > rend)  hi = rend;
        float4 ls = make_float4(0.f,0.f,0.f,0.f);
        float4 lq = make_float4(0.f,0.f,0.f,0.f);
        #pragma unroll 4
        for (int r = lo + sr; r < hi; r += SUB) {
            float4 v = s4[(size_t)r*G + g];
            ls.x += v.x; ls.y += v.y; ls.z += v.z; ls.w += v.w;
            lq.x += v.x*v.x; lq.y += v.y*v.y; lq.z += v.z*v.z; lq.w += v.w*v.w;
        }
        if (lo < hi) {
            atomicAdd(&sacc[s*C + g*4 + 0], ls.x);
            atomicAdd(&sacc[s*C + g*4 + 1], ls.y);
            atomicAdd(&sacc[s*C + g*4 + 2], ls.z);
            atomicAdd(&sacc[s*C + g*4 + 3], ls.w);
            atomicAdd(&sacc[BB*C + s*C + g*4 + 0], lq.x);
            atomicAdd(&sacc[BB*C + s*C + g*4 + 1], lq.y);
            atomicAdd(&sacc[BB*C + s*C + g*4 + 2], lq.z);
            atomicAdd(&sacc[BB*C + s*C + g*4 + 3], lq.w);
        }
    }
    __syncthreads();
    for (int i = tid; i < 2*BB*C; i += 256) atomicAdd(&dst[i], sacc[i]);
}

// ---------------- finalize mean / rsig ---------------------------------------
__global__ void k_fin(const float* __restrict__ s, float* __restrict__ mr, int C) {
    int i = blockIdx.x * blockDim.x + threadIdx.x;
    int tot = BB * C;
    if (i >= tot) return;
    int b = i / C;
    float cnt = (float)(g_bnd[b+1] - g_bnd[b]);
    float inv = cnt > 0.f ? 1.f / cnt : 0.f;
    float mean = s[i] * inv;
    float var  = s[tot + i] * inv - mean * mean;
    mr[i]       = mean;
    mr[tot + i] = rsqrtf(fmaxf(var, 0.f) + EPSN);
}

// ---------------- normalize + relu ([N,64]) ----------------------------------
__global__ void k_normrelu(const float* __restrict__ src, const float* __restrict__ mr,
                           float* __restrict__ dst, const int* __restrict__ bidx) {
    int i4 = blockIdx.x * blockDim.x + threadIdx.x;
    const int tot = NPTS*CH/4;
    int stride = gridDim.x * blockDim.x;
    const float4* s4 = (const float4*)src;
    const float4* m4 = (const float4*)mr;
    const float4* r4 = (const float4*)(mr + BB*CH);
    float4* d4 = (float4*)dst;
    for (; i4 < tot; i4 += stride) {
        int r = i4 >> 4, c4 = i4 & 15;
        int b = bidx[r];
        float4 m = m4[b*16 + c4], rs = r4[b*16 + c4];
        float4 x = s4[i4];
        float4 o;
        o.x = fmaxf((x.x - m.x)*rs.x, 0.f);
        o.y = fmaxf((x.y - m.y)*rs.y, 0.f);
        o.z = fmaxf((x.z - m.z)*rs.z, 0.f);
        o.w = fmaxf((x.w - m.w)*rs.w, 0.f);
        d4[i4] = o;
    }
}

// ---------------- sparse conv v3: staged gather, 2 pairs x 16 cols -----------
// 128 pairs/block. xs pad-68 (float4-aligned, conflict-free scalar reads).
// Thread cols = cg*4 + 16j (j=0..3): conflict-free W reads, contiguous red.v4.
__global__ void __launch_bounds__(256) k_spconv(const float* __restrict__ W2,
                                                const int* __restrict__ in_idx,
                                                const int* __restrict__ out_idx) {
    extern __shared__ float sp[];
    float* Ws = sp;                 // [64][64]   16KB
    float* xs = sp + 64*64;         // [128][68]  34.8KB
    __shared__ int sin_[128], sout_[128];
    int tid = threadIdx.x;
    int k = blockIdx.y;
    size_t kb = (size_t)k * MM;
    int m0 = blockIdx.x * 128;

    const float4* Wg = (const float4*)(W2 + (size_t)k*CH*CH);
    #pragma unroll
    for (int i = 0; i < 4; i++) ((float4*)Ws)[tid + 256*i] = Wg[tid + 256*i];

    if (tid < 128) {
        int m = m0 + tid;
        sin_[tid] = (m < MM) ? in_idx[kb + m] : -1;
    } else {
        int m = m0 + tid - 128;
        sout_[tid - 128] = (m < MM) ? out_idx[kb + m] : -1;
    }
    __syncthreads();

    // stage gathered rows (coalesced 16 threads/row)
    #pragma unroll
    for (int i = 0; i < 8; i++) {
        int lin = tid + 256*i;           // 0..2047
        int p = lin >> 4, c4 = lin & 15;
        int row = sin_[p];
        float4 v = (row >= 0) ? *(const float4*)(g_x1n + (size_t)row*CH + c4*4)
                              : make_float4(0.f,0.f,0.f,0.f);
        *(float4*)&xs[p*68 + c4*4] = v;
    }
    __syncthreads();

    int cg = tid & 3, slot = tid >> 2;   // 64 slots x 4 col-groups
    const float* xA = &xs[slot*68];
    const float* xB = &xs[(slot + 64)*68];
    int wbase = cg * 4;
    ull acc[2][4][2] = {};
    #pragma unroll 4
    for (int c = 0; c < 64; c++) {
        float xa = xA[c], xb = xB[c];
        ull ap = pack2(xa, xa), bp = pack2(xb, xb);
        const float* wrow = &Ws[c*64 + wbase];
        #pragma unroll
        for (int j = 0; j < 4; j++) {
            ulonglong2 w = *(const ulonglong2*)(wrow + j*16);
            fma2(acc[0][j][0], ap, w.x); fma2(acc[0][j][1], ap, w.y);
            fma2(acc[1][j][0], bp, w.x); fma2(acc[1][j][1], bp, w.y);
        }
    }
    int oa = sout_[slot], ob = sout_[slot + 64];
    if (oa >= 0) {
        float* dst = &g_x2[(size_t)oa*CH + wbase];
        #pragma unroll
        for (int j = 0; j < 4; j++) {
            float2 a = unpk(acc[0][j][0]), b = unpk(acc[0][j][1]);
            red_add_v4(dst + j*16, a.x, a.y, b.x, b.y);
        }
    }
    if (ob >= 0) {
        float* dst = &g_x2[(size_t)ob*CH + wbase];
        #pragma unroll
        for (int j = 0; j < 4; j++) {
            float2 a = unpk(acc[1][j][0]), b = unpk(acc[1][j][1]);
            red_add_v4(dst + j*16, a.x, a.y, b.x, b.y);
        }
    }
}

// ---------------- GEMM3: relu(IN(x2)) @ [64,256] -> g_y3 (norm fused) --------
__global__ void __launch_bounds__(256, 2) k_gemm3(const float* __restrict__ W3,
                                                  const int* __restrict__ bidx) {
    extern __shared__ float sh[];
    float* Ws = sh;              // [64][256]
    float* xs = sh + 64*256;     // [64][68]
    int tid = threadIdx.x;
    int rbase = blockIdx.x * 64;

    const float4* Wg = (const float4*)W3;
    float4* Ws4 = (float4*)Ws;
    #pragma unroll
    for (int i = 0; i < 16; i++) Ws4[tid + 256*i] = Wg[tid + 256*i];

    const float4* m4 = (const float4*)g_mr2;
    const float4* r4 = (const float4*)(g_mr2 + BB*CH);
    const float4* xg = (const float4*)g_x2;
    #pragma unroll
    for (int i = 0; i < 4; i++) {
        int lin = tid + 256*i;
        int r = lin >> 4, c4 = lin & 15;
        int gr = rbase + r;
        int b = bidx[gr];
        float4 v = xg[(size_t)gr*16 + c4];
        float4 m = m4[b*16 + c4], rs = r4[b*16 + c4];
        float4 o;
        o.x = fmaxf((v.x - m.x)*rs.x, 0.f);
        o.y = fmaxf((v.y - m.y)*rs.y, 0.f);
        o.z = fmaxf((v.z - m.z)*rs.z, 0.f);
        o.w = fmaxf((v.w - m.w)*rs.w, 0.f);
        *(float4*)&xs[r*68 + c4*4] = o;
    }
    __syncthreads();

    int dg = tid & 15, rg = tid >> 4;
    int r0 = rg * 4, col0 = dg * 16;
    ull acc[4][8] = {};
    #pragma unroll 4
    for (int c = 0; c < 64; c++) {
        const ulonglong2* wp = (const ulonglong2*)&Ws[c*256 + col0];
        ulonglong2 w0 = wp[0], w1 = wp[1], w2 = wp[2], w3 = wp[3];
        #pragma unroll
        for (int j = 0; j < 4; j++) {
            float x = xs[(r0 + j)*68 + c];
            ull xp = pack2(x, x);
            fma2(acc[j][0], xp, w0.x); fma2(acc[j][1], xp, w0.y);
            fma2(acc[j][2], xp, w1.x); fma2(acc[j][3], xp, w1.y);
            fma2(acc[j][4], xp, w2.x); fma2(acc[j][5], xp, w2.y);
            fma2(acc[j][6], xp, w3.x); fma2(acc[j][7], xp, w3.y);
        }
    }
    #pragma unroll
    for (int j = 0; j < 4; j++) {
        float* dst = &g_y3[(size_t)(rbase + r0 + j)*CIN + col0];
        #pragma unroll
        for (int q = 0; q < 4; q++) {
            float2 a = unpk(acc[j][2*q]), b = unpk(acc[j][2*q+1]);
            *(float4*)(dst + q*4) = make_float4(a.x, a.y, b.x, b.y);
        }
    }
}

// ---------------- final: relu(IN(y3) + feats) -> out -------------------------
__global__ void k_final(const float* __restrict__ feats, const int* __restrict__ bidx,
                        float* __restrict__ out) {
    int i4 = blockIdx.x * blockDim.x + threadIdx.x;
    const int tot = NPTS*CIN/4;
    int stride = gridDim.x * blockDim.x;
    const float4* y4 = (const float4*)g_y3;
    const float4* f4 = (const float4*)feats;
    const float4* m4 = (const float4*)g_mr3;
    const float4* r4 = (const float4*)(g_mr3 + BB*CIN);
    float4* o4 = (float4*)out;
    for (; i4 < tot; i4 += stride) {
        int r = i4 >> 6, c4 = i4 & 63;
        int b = bidx[r];
        float4 m = m4[b*64 + c4], rs = r4[b*64 + c4];
        float4 y = y4[i4], f = f4[i4];
        float4 o;
        o.x = fmaxf((y.x - m.x)*rs.x + f.x, 0.f);
        o.y = fmaxf((y.y - m.y)*rs.y + f.y, 0.f);
        o.z = fmaxf((y.z - m.z)*rs.z + f.z, 0.f);
        o.w = fmaxf((y.w - m.w)*rs.w + f.w, 0.f);
        o4[i4] = o;
    }
}

// ---------------- launch -----------------------------------------------------
extern "C" void kernel_launch(void* const* d_in, const int* in_sizes, int n_in,
                              void* d_out, int out_size) {
    const float* feats   = (const float*)d_in[0];
    const float* W1      = (const float*)d_in[1];
    const float* W2      = (const float*)d_in[2];
    const float* W3      = (const float*)d_in[3];
    const int*   in_idx  = (const int*)d_in[4];
    const int*   out_idx = (const int*)d_in[5];
    const int*   bidx    = (const int*)d_in[6];
    float* out = (float*)d_out;

    const int smem1 = (256*64 + 128*64) * 4;   // 98304
    const int smem3 = (64*256 + 64*68) * 4;    // 82944
    const int smemS = (64*64 + 128*68) * 4;    // 51200
    cudaFuncSetAttribute(k_gemm1,  cudaFuncAttributeMaxDynamicSharedMemorySize, smem1);
    cudaFuncSetAttribute(k_gemm3,  cudaFuncAttributeMaxDynamicSharedMemorySize, smem3);
    cudaFuncSetAttribute(k_spconv, cudaFuncAttributeMaxDynamicSharedMemorySize, smemS);

    float *p_x1, *p_x1n, *p_x2, *p_y3;
    float *p_s1, *p_s2, *p_s3, *p_mr1, *p_mr2, *p_mr3;
    cudaGetSymbolAddress((void**)&p_x1,  g_x1);
    cudaGetSymbolAddress((void**)&p_x1n, g_x1n);
    cudaGetSymbolAddress((void**)&p_x2,  g_x2);
    cudaGetSymbolAddress((void**)&p_y3,  g_y3);
    cudaGetSymbolAddress((void**)&p_s1,  g_s1);
    cudaGetSymbolAddress((void**)&p_s2,  g_s2);
    cudaGetSymbolAddress((void**)&p_s3,  g_s3);
    cudaGetSymbolAddress((void**)&p_mr1, g_mr1);
    cudaGetSymbolAddress((void**)&p_mr2, g_mr2);
    cudaGetSymbolAddress((void**)&p_mr3, g_mr3);

    k_init<<<512, 256>>>();
    k_bounds<<<(NPTS + 255)/256, 256>>>(bidx);

    // conv1 -> IN -> relu
    k_gemm1<<<(NPTS + 127)/128, 256, smem1>>>(feats, W1);
    k_stats<CH, 512><<<(NPTS + 511)/512, 256>>>(p_x1, p_s1);
    k_fin<<<1, 256>>>(p_s1, p_mr1, CH);
    k_normrelu<<<2048, 256>>>(p_x1, p_mr1, p_x1n, bidx);

    // sparse conv -> stats
    dim3 spgrid((MM + 127)/128, KK);
    k_spconv<<<spgrid, 256, smemS>>>(W2, in_idx, out_idx);
    k_stats<CH, 512><<<(NPTS + 511)/512, 256>>>(p_x2, p_s2);
    k_fin<<<1, 256>>>(p_s2, p_mr2, CH);

    // conv3 (IN+relu fused into tile load) -> IN -> residual -> relu
    k_gemm3<<<NPTS/64, 256, smem3>>>(W3, bidx);
    k_stats<CIN, 256><<<(NPTS + 255)/256, 256>>>(p_y3, p_s3);
    k_fin<<<4, 256>>>(p_s3, p_mr3, CIN);
    k_final<<<4096, 256>>>(feats, bidx, out);
}